// round 2
// baseline (speedup 1.0000x reference)
#include <cuda_runtime.h>
#include <cuda_bf16.h>

#define NV 10000
#define BB 8
#define NE 2000000
#define NB (NV * BB)

// Scratch in [N, B] (node-major, batch-contiguous) layout: each node's 8 batch
// values occupy one 32-byte chunk -> float4-pair gathers and red.v4 scatters.
__device__ float g_xt[NB];            // x transposed
__device__ float g_fx[NB];            // tanh(x)
__device__ float g_pred[NB];          // scatter accumulator (by tgt)
__device__ float g_aggr[NB];          // scatter accumulator (by src)
__device__ unsigned int g_packed[NE]; // (src<<14)|tgt, written by pass1
__device__ int   g_idx64;             // 1 if edge_index is int64, 0 if int32

// ---------------------------------------------------------------------------
// prep: transpose values -> [N,B], tanh, zero accumulators.
// Thread 0 also sniffs the edge_index dtype: indices < 10000, so int64
// (little-endian) means every odd 32-bit word is 0. P(false positive for
// int32 data over 64 words) ~ 1e-256.
__global__ void prep_kernel(const float* __restrict__ values,
                            const unsigned int* __restrict__ ei_words) {
    if (blockIdx.x == 0 && threadIdx.x == 0) {
        int is64 = 1;
        #pragma unroll
        for (int i = 0; i < 64; i++) {
            if (ei_words[2 * i + 1] != 0u) { is64 = 0; break; }
        }
        g_idx64 = is64;
    }
    int n = blockIdx.x * blockDim.x + threadIdx.x;
    if (n >= NV) return;
    float x[8], fx[8];
    #pragma unroll
    for (int b = 0; b < 8; b++) {
        x[b]  = values[b * NV + n];
        fx[b] = tanhf(x[b]);
    }
    float4* xt4 = reinterpret_cast<float4*>(g_xt)   + n * 2;
    float4* fx4 = reinterpret_cast<float4*>(g_fx)   + n * 2;
    float4* pr4 = reinterpret_cast<float4*>(g_pred) + n * 2;
    float4* ag4 = reinterpret_cast<float4*>(g_aggr) + n * 2;
    xt4[0] = make_float4(x[0], x[1], x[2], x[3]);
    xt4[1] = make_float4(x[4], x[5], x[6], x[7]);
    fx4[0] = make_float4(fx[0], fx[1], fx[2], fx[3]);
    fx4[1] = make_float4(fx[4], fx[5], fx[6], fx[7]);
    float4 z = make_float4(0.f, 0.f, 0.f, 0.f);
    pr4[0] = z; pr4[1] = z;
    ag4[0] = z; ag4[1] = z;
}

// ---------------------------------------------------------------------------
__device__ __forceinline__ void red_add_v4(float* p, float4 v) {
    asm volatile("red.global.add.v4.f32 [%0], {%1, %2, %3, %4};"
                 :: "l"(p), "f"(v.x), "f"(v.y), "f"(v.z), "f"(v.w)
                 : "memory");
}

// pass1: pred[tgt] += w * fx[src]  (2 edges/thread), and writes packed idx.
__global__ void pass1_kernel(const void* __restrict__ ei,
                             const float* __restrict__ w) {
    int i = blockIdx.x * blockDim.x + threadIdx.x;   // edge-pair index
    if (i >= NE / 2) return;
    int s0, t0, s1, t1;
    if (g_idx64) {
        const longlong2* p = (const longlong2*)ei;
        longlong2 sp = p[i];
        longlong2 tp = p[NE / 2 + i];
        s0 = (int)sp.x; s1 = (int)sp.y;
        t0 = (int)tp.x; t1 = (int)tp.y;
    } else {
        const int2* p = (const int2*)ei;
        int2 sp = p[i];
        int2 tp = p[NE / 2 + i];
        s0 = sp.x; s1 = sp.y;
        t0 = tp.x; t1 = tp.y;
    }
    float2 we = reinterpret_cast<const float2*>(w)[i];

    // side-channel for pass2: packed 14+14-bit indices
    uint2 pk = make_uint2(((unsigned)s0 << 14) | (unsigned)t0,
                          ((unsigned)s1 << 14) | (unsigned)t1);
    reinterpret_cast<uint2*>(g_packed)[i] = pk;

    const float4* fx4 = reinterpret_cast<const float4*>(g_fx);
    float4 a0 = fx4[s0 * 2], b0 = fx4[s0 * 2 + 1];
    float4 a1 = fx4[s1 * 2], b1 = fx4[s1 * 2 + 1];
    float* p0 = g_pred + (size_t)t0 * 8;
    float* p1 = g_pred + (size_t)t1 * 8;
    red_add_v4(p0,     make_float4(we.x * a0.x, we.x * a0.y, we.x * a0.z, we.x * a0.w));
    red_add_v4(p0 + 4, make_float4(we.x * b0.x, we.x * b0.y, we.x * b0.z, we.x * b0.w));
    red_add_v4(p1,     make_float4(we.y * a1.x, we.y * a1.y, we.y * a1.z, we.y * a1.w));
    red_add_v4(p1 + 4, make_float4(we.y * b1.x, we.y * b1.y, we.y * b1.z, we.y * b1.w));
}

// pass2: aggr[src] += w * (x[tgt] - pred[tgt])  (err computed on the fly)
__global__ void pass2_kernel(const float* __restrict__ w) {
    int i = blockIdx.x * blockDim.x + threadIdx.x;
    if (i >= NE / 2) return;
    uint2 pk = reinterpret_cast<const uint2*>(g_packed)[i];
    float2 we = reinterpret_cast<const float2*>(w)[i];
    int s0 = pk.x >> 14, t0 = pk.x & 16383;
    int s1 = pk.y >> 14, t1 = pk.y & 16383;

    const float4* xt4 = reinterpret_cast<const float4*>(g_xt);
    const float4* pr4 = reinterpret_cast<const float4*>(g_pred);

    float4 xa0 = xt4[t0 * 2], xb0 = xt4[t0 * 2 + 1];
    float4 pa0 = pr4[t0 * 2], pb0 = pr4[t0 * 2 + 1];
    float4 xa1 = xt4[t1 * 2], xb1 = xt4[t1 * 2 + 1];
    float4 pa1 = pr4[t1 * 2], pb1 = pr4[t1 * 2 + 1];

    float* p0 = g_aggr + (size_t)s0 * 8;
    float* p1 = g_aggr + (size_t)s1 * 8;
    red_add_v4(p0,     make_float4(we.x * (xa0.x - pa0.x), we.x * (xa0.y - pa0.y),
                                   we.x * (xa0.z - pa0.z), we.x * (xa0.w - pa0.w)));
    red_add_v4(p0 + 4, make_float4(we.x * (xb0.x - pb0.x), we.x * (xb0.y - pb0.y),
                                   we.x * (xb0.z - pb0.z), we.x * (xb0.w - pb0.w)));
    red_add_v4(p1,     make_float4(we.y * (xa1.x - pa1.x), we.y * (xa1.y - pa1.y),
                                   we.y * (xa1.z - pa1.z), we.y * (xa1.w - pa1.w)));
    red_add_v4(p1 + 4, make_float4(we.y * (xb1.x - pb1.x), we.y * (xb1.y - pb1.y),
                                   we.y * (xb1.z - pb1.z), we.y * (xb1.w - pb1.w)));
}

// ---------------------------------------------------------------------------
// out layout: [3, B*N] with inner layout [B, N] (row b, node n at b*N + n)
__global__ void final_kernel(float* __restrict__ out) {
    int n = blockIdx.x * blockDim.x + threadIdx.x;
    if (n >= NV) return;
    const float4* xt4 = reinterpret_cast<const float4*>(g_xt)   + n * 2;
    const float4* fx4 = reinterpret_cast<const float4*>(g_fx)   + n * 2;
    const float4* pr4 = reinterpret_cast<const float4*>(g_pred) + n * 2;
    const float4* ag4 = reinterpret_cast<const float4*>(g_aggr) + n * 2;
    float x[8], fx[8], pr[8], ag[8];
    float4 t;
    t = xt4[0]; x[0]=t.x; x[1]=t.y; x[2]=t.z; x[3]=t.w;
    t = xt4[1]; x[4]=t.x; x[5]=t.y; x[6]=t.z; x[7]=t.w;
    t = fx4[0]; fx[0]=t.x; fx[1]=t.y; fx[2]=t.z; fx[3]=t.w;
    t = fx4[1]; fx[4]=t.x; fx[5]=t.y; fx[6]=t.z; fx[7]=t.w;
    t = pr4[0]; pr[0]=t.x; pr[1]=t.y; pr[2]=t.z; pr[3]=t.w;
    t = pr4[1]; pr[4]=t.x; pr[5]=t.y; pr[6]=t.z; pr[7]=t.w;
    t = ag4[0]; ag[0]=t.x; ag[1]=t.y; ag[2]=t.z; ag[3]=t.w;
    t = ag4[1]; ag[4]=t.x; ag[5]=t.y; ag[6]=t.z; ag[7]=t.w;
    #pragma unroll
    for (int b = 0; b < 8; b++) {
        float err = x[b] - pr[b];
        float dx  = err - (1.0f - fx[b] * fx[b]) * ag[b];
        int o = b * NV + n;
        out[o]          = pr[b];
        out[NB + o]     = err;
        out[2 * NB + o] = dx;
    }
}

// ---------------------------------------------------------------------------
extern "C" void kernel_launch(void* const* d_in, const int* in_sizes, int n_in,
                              void* d_out, int out_size) {
    const float* values  = (const float*)d_in[0];
    const float* weights = (const float*)d_in[1];
    const void*  ei      = (const void*)d_in[2];
    float* out = (float*)d_out;

    const int TB = 256;
    prep_kernel<<<(NV + TB - 1) / TB, TB>>>(values, (const unsigned int*)ei);
    pass1_kernel<<<(NE / 2 + TB - 1) / TB, TB>>>(ei, weights);
    pass2_kernel<<<(NE / 2 + TB - 1) / TB, TB>>>(weights);
    final_kernel<<<(NV + TB - 1) / TB, TB>>>(out);
}

// round 3
// speedup vs baseline: 1.0472x; 1.0472x over previous
#include <cuda_runtime.h>
#include <cuda_bf16.h>

#define NV 10000
#define BB 8
#define NE 2000000
#define NB (NV * BB)

// Node tables in [N, B] layout: each node's 8 batch values = one 32B chunk.
__device__ float g_xt[NB];            // x transposed
__device__ float g_fx[NB];            // tanh(x)
__device__ float g_pred[NB];          // scatter accumulator (by tgt)
__device__ float g_err[NB];           // x - pred
__device__ float g_aggr[NB];          // scatter accumulator (by src)
__device__ unsigned int g_packed[NE]; // (src<<14)|tgt, written by pass1
__device__ int   g_idx64;             // 1 if edge_index is int64

// ---------------------------------------------------------------------------
// prep: transpose values -> [N,B], tanh, zero accumulators, sniff idx dtype.
__global__ __launch_bounds__(256) void prep_kernel(
        const float* __restrict__ values,
        const unsigned int* __restrict__ ei_words) {
    if (blockIdx.x == 0 && threadIdx.x == 0) {
        int is64 = 1;
        #pragma unroll
        for (int i = 0; i < 64; i++) {
            if (ei_words[2 * i + 1] != 0u) { is64 = 0; break; }
        }
        g_idx64 = is64;
    }
    int n = blockIdx.x * blockDim.x + threadIdx.x;
    if (n >= NV) return;
    float x[8], fx[8];
    #pragma unroll
    for (int b = 0; b < 8; b++) {
        x[b]  = values[b * NV + n];
        fx[b] = tanhf(x[b]);
    }
    float4* xt4 = reinterpret_cast<float4*>(g_xt)   + n * 2;
    float4* fx4 = reinterpret_cast<float4*>(g_fx)   + n * 2;
    float4* pr4 = reinterpret_cast<float4*>(g_pred) + n * 2;
    float4* ag4 = reinterpret_cast<float4*>(g_aggr) + n * 2;
    xt4[0] = make_float4(x[0], x[1], x[2], x[3]);
    xt4[1] = make_float4(x[4], x[5], x[6], x[7]);
    fx4[0] = make_float4(fx[0], fx[1], fx[2], fx[3]);
    fx4[1] = make_float4(fx[4], fx[5], fx[6], fx[7]);
    float4 z = make_float4(0.f, 0.f, 0.f, 0.f);
    pr4[0] = z; pr4[1] = z;
    ag4[0] = z; ag4[1] = z;
}

// ---------------------------------------------------------------------------
__device__ __forceinline__ void red_add_v4(float* p, float4 v) {
    asm volatile("red.global.add.v4.f32 [%0], {%1, %2, %3, %4};"
                 :: "l"(p), "f"(v.x), "f"(v.y), "f"(v.z), "f"(v.w)
                 : "memory");
}

// pass1: pred[tgt] += w * fx[src]  (2 edges/thread); writes packed indices.
__global__ __launch_bounds__(256) void pass1_kernel(
        const void* __restrict__ ei, const float* __restrict__ w) {
    int i = blockIdx.x * blockDim.x + threadIdx.x;   // edge-pair index
    if (i >= NE / 2) return;
    int s0, t0, s1, t1;
    if (g_idx64) {
        const longlong2* p = (const longlong2*)ei;
        longlong2 sp = p[i];
        longlong2 tp = p[NE / 2 + i];
        s0 = (int)sp.x; s1 = (int)sp.y;
        t0 = (int)tp.x; t1 = (int)tp.y;
    } else {
        const int2* p = (const int2*)ei;
        int2 sp = p[i];
        int2 tp = p[NE / 2 + i];
        s0 = sp.x; s1 = sp.y;
        t0 = tp.x; t1 = tp.y;
    }
    float2 we = reinterpret_cast<const float2*>(w)[i];

    reinterpret_cast<uint2*>(g_packed)[i] =
        make_uint2(((unsigned)s0 << 14) | (unsigned)t0,
                   ((unsigned)s1 << 14) | (unsigned)t1);

    const float4* fx4 = reinterpret_cast<const float4*>(g_fx);
    float4 a0 = fx4[s0 * 2], b0 = fx4[s0 * 2 + 1];
    float4 a1 = fx4[s1 * 2], b1 = fx4[s1 * 2 + 1];
    float* p0 = g_pred + (size_t)t0 * 8;
    float* p1 = g_pred + (size_t)t1 * 8;
    red_add_v4(p0,     make_float4(we.x * a0.x, we.x * a0.y, we.x * a0.z, we.x * a0.w));
    red_add_v4(p0 + 4, make_float4(we.x * b0.x, we.x * b0.y, we.x * b0.z, we.x * b0.w));
    red_add_v4(p1,     make_float4(we.y * a1.x, we.y * a1.y, we.y * a1.z, we.y * a1.w));
    red_add_v4(p1 + 4, make_float4(we.y * b1.x, we.y * b1.y, we.y * b1.z, we.y * b1.w));
}

// ---------------------------------------------------------------------------
__global__ __launch_bounds__(256) void err_kernel() {
    int i = blockIdx.x * blockDim.x + threadIdx.x;   // float4 index
    if (i >= NB / 4) return;
    const float4* xt4 = reinterpret_cast<const float4*>(g_xt);
    const float4* pr4 = reinterpret_cast<const float4*>(g_pred);
    float4 x = xt4[i], p = pr4[i];
    reinterpret_cast<float4*>(g_err)[i] =
        make_float4(x.x - p.x, x.y - p.y, x.z - p.z, x.w - p.w);
}

// ---------------------------------------------------------------------------
// pass2: aggr[src] += w * err[tgt]  (4 edges/thread, packed indices)
__global__ __launch_bounds__(256) void pass2_kernel(const float* __restrict__ w) {
    int i = blockIdx.x * blockDim.x + threadIdx.x;   // edge-quad index
    if (i >= NE / 4) return;
    uint4  pk = reinterpret_cast<const uint4*>(g_packed)[i];
    float4 we = reinterpret_cast<const float4*>(w)[i];
    const float4* er4 = reinterpret_cast<const float4*>(g_err);

    unsigned pks[4] = {pk.x, pk.y, pk.z, pk.w};
    float    ws[4]  = {we.x, we.y, we.z, we.w};
    #pragma unroll
    for (int k = 0; k < 4; k++) {
        int s = pks[k] >> 14, t = pks[k] & 16383;
        float4 a = er4[t * 2], b = er4[t * 2 + 1];
        float wk = ws[k];
        float* p = g_aggr + (size_t)s * 8;
        red_add_v4(p,     make_float4(wk * a.x, wk * a.y, wk * a.z, wk * a.w));
        red_add_v4(p + 4, make_float4(wk * b.x, wk * b.y, wk * b.z, wk * b.w));
    }
}

// ---------------------------------------------------------------------------
// out layout: [3, B*N], inner [B, N] (row b, node n at b*N + n)
__global__ __launch_bounds__(256) void final_kernel(float* __restrict__ out) {
    int n = blockIdx.x * blockDim.x + threadIdx.x;
    if (n >= NV) return;
    const float4* fx4 = reinterpret_cast<const float4*>(g_fx)   + n * 2;
    const float4* pr4 = reinterpret_cast<const float4*>(g_pred) + n * 2;
    const float4* er4 = reinterpret_cast<const float4*>(g_err)  + n * 2;
    const float4* ag4 = reinterpret_cast<const float4*>(g_aggr) + n * 2;
    float fx[8], pr[8], er[8], ag[8];
    float4 t;
    t = fx4[0]; fx[0]=t.x; fx[1]=t.y; fx[2]=t.z; fx[3]=t.w;
    t = fx4[1]; fx[4]=t.x; fx[5]=t.y; fx[6]=t.z; fx[7]=t.w;
    t = pr4[0]; pr[0]=t.x; pr[1]=t.y; pr[2]=t.z; pr[3]=t.w;
    t = pr4[1]; pr[4]=t.x; pr[5]=t.y; pr[6]=t.z; pr[7]=t.w;
    t = er4[0]; er[0]=t.x; er[1]=t.y; er[2]=t.z; er[3]=t.w;
    t = er4[1]; er[4]=t.x; er[5]=t.y; er[6]=t.z; er[7]=t.w;
    t = ag4[0]; ag[0]=t.x; ag[1]=t.y; ag[2]=t.z; ag[3]=t.w;
    t = ag4[1]; ag[4]=t.x; ag[5]=t.y; ag[6]=t.z; ag[7]=t.w;
    #pragma unroll
    for (int b = 0; b < 8; b++) {
        float dx = er[b] - (1.0f - fx[b] * fx[b]) * ag[b];
        int o = b * NV + n;
        out[o]          = pr[b];
        out[NB + o]     = er[b];
        out[2 * NB + o] = dx;
    }
}

// ---------------------------------------------------------------------------
extern "C" void kernel_launch(void* const* d_in, const int* in_sizes, int n_in,
                              void* d_out, int out_size) {
    const float* values  = (const float*)d_in[0];
    const float* weights = (const float*)d_in[1];
    const void*  ei      = (const void*)d_in[2];
    float* out = (float*)d_out;

    const int TB = 256;
    prep_kernel <<<(NV + TB - 1) / TB, TB>>>(values, (const unsigned int*)ei);
    pass1_kernel<<<(NE / 2 + TB - 1) / TB, TB>>>(ei, weights);
    err_kernel  <<<(NB / 4 + TB - 1) / TB, TB>>>();
    pass2_kernel<<<(NE / 4 + TB - 1) / TB, TB>>>(weights);
    final_kernel<<<(NV + TB - 1) / TB, TB>>>(out);
}

// round 4
// speedup vs baseline: 1.0555x; 1.0079x over previous
#include <cuda_runtime.h>
#include <cuda_bf16.h>

#define NV 10000
#define BB 8
#define NE 2000000
#define NB (NV * BB)

// Node tables in [N, B] layout: each node's 8 batch values = one 32B chunk.
__device__ float g_xt[NB];            // x transposed
__device__ float g_fx[NB];            // tanh(x)
__device__ float g_pred[NB];          // scatter accumulator (by tgt)
__device__ float g_err[NB];           // x - pred
__device__ float g_aggr[NB];          // scatter accumulator (by src)
__device__ unsigned int g_packed[NE]; // (src<<14)|tgt, written by pass1
__device__ int   g_idx64;             // 1 if edge_index is int64

// ---------------------------------------------------------------------------
// prep: transpose values -> [N,B], tanh, zero accumulators, sniff idx dtype.
__global__ __launch_bounds__(256) void prep_kernel(
        const float* __restrict__ values,
        const unsigned int* __restrict__ ei_words) {
    if (blockIdx.x == 0 && threadIdx.x == 0) {
        int is64 = 1;
        #pragma unroll
        for (int i = 0; i < 64; i++) {
            if (ei_words[2 * i + 1] != 0u) { is64 = 0; break; }
        }
        g_idx64 = is64;
    }
    int n = blockIdx.x * blockDim.x + threadIdx.x;
    if (n >= NV) return;
    float x[8], fx[8];
    #pragma unroll
    for (int b = 0; b < 8; b++) {
        x[b]  = values[b * NV + n];
        fx[b] = tanhf(x[b]);
    }
    float4* xt4 = reinterpret_cast<float4*>(g_xt)   + n * 2;
    float4* fx4 = reinterpret_cast<float4*>(g_fx)   + n * 2;
    float4* pr4 = reinterpret_cast<float4*>(g_pred) + n * 2;
    float4* ag4 = reinterpret_cast<float4*>(g_aggr) + n * 2;
    xt4[0] = make_float4(x[0], x[1], x[2], x[3]);
    xt4[1] = make_float4(x[4], x[5], x[6], x[7]);
    fx4[0] = make_float4(fx[0], fx[1], fx[2], fx[3]);
    fx4[1] = make_float4(fx[4], fx[5], fx[6], fx[7]);
    float4 z = make_float4(0.f, 0.f, 0.f, 0.f);
    pr4[0] = z; pr4[1] = z;
    ag4[0] = z; ag4[1] = z;
}

// ---------------------------------------------------------------------------
// NOTE: no "memory" clobber — the compiler may hoist independent loads above
// these (desired: batch all gathers, then fire all reductions). volatile
// alone guarantees the op is emitted exactly once.
__device__ __forceinline__ void red_add_v4(float* p, float4 v) {
    asm volatile("red.global.add.v4.f32 [%0], {%1, %2, %3, %4};"
                 :: "l"(p), "f"(v.x), "f"(v.y), "f"(v.z), "f"(v.w));
}

// ---------------------------------------------------------------------------
// pass1: pred[tgt] += w * fx[src]  (2 edges/thread); writes packed indices.
// Structure: all loads first, then all reductions.
__global__ __launch_bounds__(256) void pass1_kernel(
        const void* __restrict__ ei, const float* __restrict__ w) {
    int i = blockIdx.x * blockDim.x + threadIdx.x;   // edge-pair index
    if (i >= NE / 2) return;
    int s0, t0, s1, t1;
    if (g_idx64) {
        const longlong2* p = (const longlong2*)ei;
        longlong2 sp = p[i];
        longlong2 tp = p[NE / 2 + i];
        s0 = (int)sp.x; s1 = (int)sp.y;
        t0 = (int)tp.x; t1 = (int)tp.y;
    } else {
        const int2* p = (const int2*)ei;
        int2 sp = p[i];
        int2 tp = p[NE / 2 + i];
        s0 = sp.x; s1 = sp.y;
        t0 = tp.x; t1 = tp.y;
    }
    float2 we = reinterpret_cast<const float2*>(w)[i];

    const float4* fx4 = reinterpret_cast<const float4*>(g_fx);
    // all gathers issued back-to-back (4 independent LDG.128)
    float4 a0 = __ldg(fx4 + s0 * 2);
    float4 b0 = __ldg(fx4 + s0 * 2 + 1);
    float4 a1 = __ldg(fx4 + s1 * 2);
    float4 b1 = __ldg(fx4 + s1 * 2 + 1);

    reinterpret_cast<uint2*>(g_packed)[i] =
        make_uint2(((unsigned)s0 << 14) | (unsigned)t0,
                   ((unsigned)s1 << 14) | (unsigned)t1);

    float* p0 = g_pred + (size_t)t0 * 8;
    float* p1 = g_pred + (size_t)t1 * 8;
    red_add_v4(p0,     make_float4(we.x * a0.x, we.x * a0.y, we.x * a0.z, we.x * a0.w));
    red_add_v4(p0 + 4, make_float4(we.x * b0.x, we.x * b0.y, we.x * b0.z, we.x * b0.w));
    red_add_v4(p1,     make_float4(we.y * a1.x, we.y * a1.y, we.y * a1.z, we.y * a1.w));
    red_add_v4(p1 + 4, make_float4(we.y * b1.x, we.y * b1.y, we.y * b1.z, we.y * b1.w));
}

// ---------------------------------------------------------------------------
__global__ __launch_bounds__(256) void err_kernel() {
    int i = blockIdx.x * blockDim.x + threadIdx.x;   // float4 index
    if (i >= NB / 4) return;
    const float4* xt4 = reinterpret_cast<const float4*>(g_xt);
    const float4* pr4 = reinterpret_cast<const float4*>(g_pred);
    float4 x = xt4[i], p = pr4[i];
    reinterpret_cast<float4*>(g_err)[i] =
        make_float4(x.x - p.x, x.y - p.y, x.z - p.z, x.w - p.w);
}

// ---------------------------------------------------------------------------
// pass2: aggr[src] += w * err[tgt]  (4 edges/thread, packed indices)
// Structure: load 4 packed + 4 weights, issue ALL 8 gathers, then 8 reds.
__global__ __launch_bounds__(256) void pass2_kernel(const float* __restrict__ w) {
    int i = blockIdx.x * blockDim.x + threadIdx.x;   // edge-quad index
    if (i >= NE / 4) return;
    uint4  pk = reinterpret_cast<const uint4*>(g_packed)[i];
    float4 we = reinterpret_cast<const float4*>(w)[i];
    const float4* er4 = reinterpret_cast<const float4*>(g_err);

    int s[4], t[4];
    s[0] = pk.x >> 14; t[0] = pk.x & 16383;
    s[1] = pk.y >> 14; t[1] = pk.y & 16383;
    s[2] = pk.z >> 14; t[2] = pk.z & 16383;
    s[3] = pk.w >> 14; t[3] = pk.w & 16383;
    float ws[4] = {we.x, we.y, we.z, we.w};

    float4 a[4], b[4];
    #pragma unroll
    for (int k = 0; k < 4; k++) {   // 8 independent LDG.128 in flight
        a[k] = __ldg(er4 + t[k] * 2);
        b[k] = __ldg(er4 + t[k] * 2 + 1);
    }
    #pragma unroll
    for (int k = 0; k < 4; k++) {
        float wk = ws[k];
        float* p = g_aggr + (size_t)s[k] * 8;
        red_add_v4(p,     make_float4(wk * a[k].x, wk * a[k].y, wk * a[k].z, wk * a[k].w));
        red_add_v4(p + 4, make_float4(wk * b[k].x, wk * b[k].y, wk * b[k].z, wk * b[k].w));
    }
}

// ---------------------------------------------------------------------------
// out layout: [3, B*N], inner [B, N] (row b, node n at b*N + n)
__global__ __launch_bounds__(256) void final_kernel(float* __restrict__ out) {
    int n = blockIdx.x * blockDim.x + threadIdx.x;
    if (n >= NV) return;
    const float4* fx4 = reinterpret_cast<const float4*>(g_fx)   + n * 2;
    const float4* pr4 = reinterpret_cast<const float4*>(g_pred) + n * 2;
    const float4* er4 = reinterpret_cast<const float4*>(g_err)  + n * 2;
    const float4* ag4 = reinterpret_cast<const float4*>(g_aggr) + n * 2;
    float fx[8], pr[8], er[8], ag[8];
    float4 t;
    t = fx4[0]; fx[0]=t.x; fx[1]=t.y; fx[2]=t.z; fx[3]=t.w;
    t = fx4[1]; fx[4]=t.x; fx[5]=t.y; fx[6]=t.z; fx[7]=t.w;
    t = pr4[0]; pr[0]=t.x; pr[1]=t.y; pr[2]=t.z; pr[3]=t.w;
    t = pr4[1]; pr[4]=t.x; pr[5]=t.y; pr[6]=t.z; pr[7]=t.w;
    t = er4[0]; er[0]=t.x; er[1]=t.y; er[2]=t.z; er[3]=t.w;
    t = er4[1]; er[4]=t.x; er[5]=t.y; er[6]=t.z; er[7]=t.w;
    t = ag4[0]; ag[0]=t.x; ag[1]=t.y; ag[2]=t.z; ag[3]=t.w;
    t = ag4[1]; ag[4]=t.x; ag[5]=t.y; ag[6]=t.z; ag[7]=t.w;
    #pragma unroll
    for (int b = 0; b < 8; b++) {
        float dx = er[b] - (1.0f - fx[b] * fx[b]) * ag[b];
        int o = b * NV + n;
        out[o]          = pr[b];
        out[NB + o]     = er[b];
        out[2 * NB + o] = dx;
    }
}

// ---------------------------------------------------------------------------
extern "C" void kernel_launch(void* const* d_in, const int* in_sizes, int n_in,
                              void* d_out, int out_size) {
    const float* values  = (const float*)d_in[0];
    const float* weights = (const float*)d_in[1];
    const void*  ei      = (const void*)d_in[2];
    float* out = (float*)d_out;

    const int TB = 256;
    prep_kernel <<<(NV + TB - 1) / TB, TB>>>(values, (const unsigned int*)ei);
    pass1_kernel<<<(NE / 2 + TB - 1) / TB, TB>>>(ei, weights);
    err_kernel  <<<(NB / 4 + TB - 1) / TB, TB>>>();
    pass2_kernel<<<(NE / 4 + TB - 1) / TB, TB>>>(weights);
    final_kernel<<<(NV + TB - 1) / TB, TB>>>(out);
}

// round 5
// speedup vs baseline: 1.1412x; 1.0812x over previous
#include <cuda_runtime.h>
#include <cuda_bf16.h>

#define NV 10000
#define BB 8
#define NE 2000000
#define NB (NV * BB)

// Node tables in [N, B] layout: each node's 8 batch values = one 32B chunk.
__device__ float g_xt[NB];            // x transposed
__device__ float g_fx[NB];            // tanh(x)
__device__ float g_pred[NB];          // scatter accumulator (by tgt)
__device__ float g_err[NB];           // x - pred
__device__ float g_aggr[NB];          // scatter accumulator (by src)
__device__ unsigned int g_packed[NE]; // (src<<14)|tgt, written by pass1
__device__ int   g_idx64;             // 1 if edge_index is int64

// ---------------------------------------------------------------------------
// prep: transpose values -> [N,B], tanh, zero accumulators, sniff idx dtype.
__global__ __launch_bounds__(256) void prep_kernel(
        const float* __restrict__ values,
        const unsigned int* __restrict__ ei_words) {
    if (blockIdx.x == 0 && threadIdx.x == 0) {
        int is64 = 1;
        #pragma unroll
        for (int i = 0; i < 64; i++) {
            if (ei_words[2 * i + 1] != 0u) { is64 = 0; break; }
        }
        g_idx64 = is64;
    }
    int n = blockIdx.x * blockDim.x + threadIdx.x;
    if (n >= NV) return;
    float x[8], fx[8];
    #pragma unroll
    for (int b = 0; b < 8; b++) {
        x[b]  = values[b * NV + n];
        fx[b] = tanhf(x[b]);
    }
    float4* xt4 = reinterpret_cast<float4*>(g_xt)   + n * 2;
    float4* fx4 = reinterpret_cast<float4*>(g_fx)   + n * 2;
    float4* pr4 = reinterpret_cast<float4*>(g_pred) + n * 2;
    float4* ag4 = reinterpret_cast<float4*>(g_aggr) + n * 2;
    xt4[0] = make_float4(x[0], x[1], x[2], x[3]);
    xt4[1] = make_float4(x[4], x[5], x[6], x[7]);
    fx4[0] = make_float4(fx[0], fx[1], fx[2], fx[3]);
    fx4[1] = make_float4(fx[4], fx[5], fx[6], fx[7]);
    float4 z = make_float4(0.f, 0.f, 0.f, 0.f);
    pr4[0] = z; pr4[1] = z;
    ag4[0] = z; ag4[1] = z;
}

// ---------------------------------------------------------------------------
__device__ __forceinline__ void red_add_v4(float* p, float4 v) {
    asm volatile("red.global.add.v4.f32 [%0], {%1, %2, %3, %4};"
                 :: "l"(p), "f"(v.x), "f"(v.y), "f"(v.z), "f"(v.w));
}

// ===========================================================================
// Cooperative edge passes: 8 lanes per edge (4 edges per warp-group step).
// Lane j of an 8-lane group loads batch element (j&7) of its edge: the 8
// lanes hit ONE 32B chunk => 1 L1tex line per edge instead of 2 random 16B
// lines. Then 3 warp-wide shfl_down pack each group's 8 floats into lanes
// {0,4} (mod 8) as float4, which fire red.v4 (2 lane-ops/edge, unchanged).
//
// Each warp handles 32 edges as 8 groups-of-4, all loads batched first.
// ===========================================================================

#define GPW 8   // groups (of 4 edges) per warp per launch

// pass1: pred[tgt] += w * fx[src]; also writes packed (src<<14)|tgt.
__global__ __launch_bounds__(256) void pass1_kernel(
        const void* __restrict__ ei, const float* __restrict__ w) {
    int tid  = blockIdx.x * blockDim.x + threadIdx.x;
    int warp = tid >> 5;
    int lane = tid & 31;
    int sub  = lane >> 3;      // which edge of the group (0..3)
    int b    = lane & 7;       // batch element this lane handles
    int g0   = warp * GPW;     // first group index

    int   s[GPW], t[GPW];
    float we[GPW], v[GPW];
    const int idx64 = g_idx64;

    // batch all edge-stream loads + all gathers (independent LDGs)
    #pragma unroll
    for (int g = 0; g < GPW; g++) {
        int e4 = g0 + g;
        int e  = e4 * 4 + sub;
        bool ok = (e4 < NE / 4);
        int ec = ok ? e : 0;
        if (idx64) {
            const long long* p = (const long long*)ei;
            s[g] = (int)__ldg(p + ec);
            t[g] = (int)__ldg(p + NE + ec);
        } else {
            const int* p = (const int*)ei;
            s[g] = __ldg(p + ec);
            t[g] = __ldg(p + NE + ec);
        }
        we[g] = __ldg(w + ec);
    }
    #pragma unroll
    for (int g = 0; g < GPW; g++) {
        v[g] = we[g] * __ldg(g_fx + s[g] * 8 + b);   // 8 lanes: one 32B chunk
    }

    // pack + reduce
    #pragma unroll
    for (int g = 0; g < GPW; g++) {
        int e4 = g0 + g;
        bool ok = (e4 < NE / 4);
        float v1 = __shfl_down_sync(0xffffffffu, v[g], 1);
        float v2 = __shfl_down_sync(0xffffffffu, v[g], 2);
        float v3 = __shfl_down_sync(0xffffffffu, v[g], 3);
        if (ok) {
            if (b == 0) {
                int e = e4 * 4 + sub;
                g_packed[e] = ((unsigned)s[g] << 14) | (unsigned)t[g];
            }
            if ((lane & 3) == 0) {   // lanes 0,4,... : elems b..b+3 of edge
                red_add_v4(g_pred + (size_t)t[g] * 8 + b,
                           make_float4(v[g], v1, v2, v3));
            }
        }
    }
}

// ---------------------------------------------------------------------------
__global__ __launch_bounds__(256) void err_kernel() {
    int i = blockIdx.x * blockDim.x + threadIdx.x;   // float4 index
    if (i >= NB / 4) return;
    const float4* xt4 = reinterpret_cast<const float4*>(g_xt);
    const float4* pr4 = reinterpret_cast<const float4*>(g_pred);
    float4 x = xt4[i], p = pr4[i];
    reinterpret_cast<float4*>(g_err)[i] =
        make_float4(x.x - p.x, x.y - p.y, x.z - p.z, x.w - p.w);
}

// ---------------------------------------------------------------------------
// pass2: aggr[src] += w * err[tgt]  (coop layout, packed indices)
__global__ __launch_bounds__(256) void pass2_kernel(const float* __restrict__ w) {
    int tid  = blockIdx.x * blockDim.x + threadIdx.x;
    int warp = tid >> 5;
    int lane = tid & 31;
    int sub  = lane >> 3;
    int b    = lane & 7;
    int g0   = warp * GPW;

    int   s[GPW], t[GPW];
    float we[GPW], v[GPW];

    #pragma unroll
    for (int g = 0; g < GPW; g++) {
        int e4 = g0 + g;
        int e  = e4 * 4 + sub;
        bool ok = (e4 < NE / 4);
        int ec = ok ? e : 0;
        unsigned pk = __ldg(g_packed + ec);
        s[g] = (int)(pk >> 14);
        t[g] = (int)(pk & 16383u);
        we[g] = __ldg(w + ec);
    }
    #pragma unroll
    for (int g = 0; g < GPW; g++) {
        v[g] = we[g] * __ldg(g_err + t[g] * 8 + b);
    }
    #pragma unroll
    for (int g = 0; g < GPW; g++) {
        int e4 = g0 + g;
        bool ok = (e4 < NE / 4);
        float v1 = __shfl_down_sync(0xffffffffu, v[g], 1);
        float v2 = __shfl_down_sync(0xffffffffu, v[g], 2);
        float v3 = __shfl_down_sync(0xffffffffu, v[g], 3);
        if (ok && (lane & 3) == 0) {
            red_add_v4(g_aggr + (size_t)s[g] * 8 + b,
                       make_float4(v[g], v1, v2, v3));
        }
    }
}

// ---------------------------------------------------------------------------
// out layout: [3, B*N], inner [B, N] (row b, node n at b*N + n)
__global__ __launch_bounds__(256) void final_kernel(float* __restrict__ out) {
    int n = blockIdx.x * blockDim.x + threadIdx.x;
    if (n >= NV) return;
    const float4* fx4 = reinterpret_cast<const float4*>(g_fx)   + n * 2;
    const float4* pr4 = reinterpret_cast<const float4*>(g_pred) + n * 2;
    const float4* er4 = reinterpret_cast<const float4*>(g_err)  + n * 2;
    const float4* ag4 = reinterpret_cast<const float4*>(g_aggr) + n * 2;
    float fx[8], pr[8], er[8], ag[8];
    float4 t;
    t = fx4[0]; fx[0]=t.x; fx[1]=t.y; fx[2]=t.z; fx[3]=t.w;
    t = fx4[1]; fx[4]=t.x; fx[5]=t.y; fx[6]=t.z; fx[7]=t.w;
    t = pr4[0]; pr[0]=t.x; pr[1]=t.y; pr[2]=t.z; pr[3]=t.w;
    t = pr4[1]; pr[4]=t.x; pr[5]=t.y; pr[6]=t.z; pr[7]=t.w;
    t = er4[0]; er[0]=t.x; er[1]=t.y; er[2]=t.z; er[3]=t.w;
    t = er4[1]; er[4]=t.x; er[5]=t.y; er[6]=t.z; er[7]=t.w;
    t = ag4[0]; ag[0]=t.x; ag[1]=t.y; ag[2]=t.z; ag[3]=t.w;
    t = ag4[1]; ag[4]=t.x; ag[5]=t.y; ag[6]=t.z; ag[7]=t.w;
    #pragma unroll
    for (int b = 0; b < 8; b++) {
        float dx = er[b] - (1.0f - fx[b] * fx[b]) * ag[b];
        int o = b * NV + n;
        out[o]          = pr[b];
        out[NB + o]     = er[b];
        out[2 * NB + o] = dx;
    }
}

// ---------------------------------------------------------------------------
extern "C" void kernel_launch(void* const* d_in, const int* in_sizes, int n_in,
                              void* d_out, int out_size) {
    const float* values  = (const float*)d_in[0];
    const float* weights = (const float*)d_in[1];
    const void*  ei      = (const void*)d_in[2];
    float* out = (float*)d_out;

    const int TB = 256;
    // edge kernels: 1 warp per 32 edges (8 groups of 4)
    int ngroups = NE / 4;                        // 500000
    int nwarps  = (ngroups + GPW - 1) / GPW;     // 62500
    int nblocks = (nwarps * 32 + TB - 1) / TB;   // 7813

    prep_kernel <<<(NV + TB - 1) / TB, TB>>>(values, (const unsigned int*)ei);
    pass1_kernel<<<nblocks, TB>>>(ei, weights);
    err_kernel  <<<(NB / 4 + TB - 1) / TB, TB>>>();
    pass2_kernel<<<nblocks, TB>>>(weights);
    final_kernel<<<(NV + TB - 1) / TB, TB>>>(out);
}

// round 6
// speedup vs baseline: 1.3058x; 1.1442x over previous
#include <cuda_runtime.h>
#include <cuda_bf16.h>

#define NV 10000
#define BB 8
#define NE 2000000
#define NB (NV * BB)

// Node tables in [N, B] layout: each node's 8 batch values = one 32B chunk.
__device__ float g_xt[NB];            // x transposed
__device__ float g_fx[NB];            // tanh(x)
__device__ float g_pred[NB];          // scatter accumulator (by tgt)
__device__ float g_err[NB];           // x - pred
__device__ float g_aggr[NB];          // scatter accumulator (by src)
__device__ unsigned int g_packed[NE]; // (src<<14)|tgt, written by pass1
__device__ int   g_idx64;             // 1 if edge_index is int64

// ---------------------------------------------------------------------------
// prep: transpose values -> [N,B], tanh, zero accumulators, sniff idx dtype.
__global__ __launch_bounds__(256) void prep_kernel(
        const float* __restrict__ values,
        const unsigned int* __restrict__ ei_words) {
    if (blockIdx.x == 0 && threadIdx.x == 0) {
        int is64 = 1;
        #pragma unroll
        for (int i = 0; i < 64; i++) {
            if (ei_words[2 * i + 1] != 0u) { is64 = 0; break; }
        }
        g_idx64 = is64;
    }
    int n = blockIdx.x * blockDim.x + threadIdx.x;
    if (n >= NV) return;
    float x[8], fx[8];
    #pragma unroll
    for (int b = 0; b < 8; b++) {
        x[b]  = values[b * NV + n];
        fx[b] = tanhf(x[b]);
    }
    float4* xt4 = reinterpret_cast<float4*>(g_xt)   + n * 2;
    float4* fx4 = reinterpret_cast<float4*>(g_fx)   + n * 2;
    float4* pr4 = reinterpret_cast<float4*>(g_pred) + n * 2;
    float4* ag4 = reinterpret_cast<float4*>(g_aggr) + n * 2;
    xt4[0] = make_float4(x[0], x[1], x[2], x[3]);
    xt4[1] = make_float4(x[4], x[5], x[6], x[7]);
    fx4[0] = make_float4(fx[0], fx[1], fx[2], fx[3]);
    fx4[1] = make_float4(fx[4], fx[5], fx[6], fx[7]);
    float4 z = make_float4(0.f, 0.f, 0.f, 0.f);
    pr4[0] = z; pr4[1] = z;
    ag4[0] = z; ag4[1] = z;
}

// ---------------------------------------------------------------------------
__device__ __forceinline__ void red_add_v4(float* p, float4 v) {
    asm volatile("red.global.add.v4.f32 [%0], {%1, %2, %3, %4};"
                 :: "l"(p), "f"(v.x), "f"(v.y), "f"(v.z), "f"(v.w));
}

// ===========================================================================
// Edge passes: 2 lanes per edge, zero shuffles.
// Lane pair (2k, 2k+1) owns one edge; parity p = lane&1 selects which 16B
// half of the node's 32B batch-chunk this lane handles. One LDG.128 gathers
// (adjacent lanes -> same 32B chunk -> 1 line/edge); one full-warp red.v4
// scatters (pairs adjacent -> minimal lines); no shfl, no predication.
// Each warp processes 16*EPT edges with all loads batched first.
// ===========================================================================

#define EPT 4   // warp-steps per thread (16 edges per warp-step)

// pass1: pred[tgt] += w * fx[src]; also writes packed (src<<14)|tgt.
__global__ __launch_bounds__(256) void pass1_kernel(
        const void* __restrict__ ei, const float* __restrict__ w) {
    int tid  = blockIdx.x * blockDim.x + threadIdx.x;
    int warp = tid >> 5;
    int lane = tid & 31;
    int p    = lane & 1;        // 16B half selector
    int eo   = lane >> 1;       // edge slot within warp-step (0..15)
    int base = warp * (16 * EPT) + eo;

    int   s[EPT], t[EPT];
    float we[EPT];
    float4 v[EPT];
    const int idx64 = g_idx64;

    #pragma unroll
    for (int k = 0; k < EPT; k++) {
        int e  = base + k * 16;
        int ec = (e < NE) ? e : 0;
        if (idx64) {
            s[k] = (int)__ldg((const long long*)ei + ec);
            t[k] = (int)__ldg((const long long*)ei + NE + ec);
        } else {
            s[k] = __ldg((const int*)ei + ec);
            t[k] = __ldg((const int*)ei + NE + ec);
        }
        we[k] = __ldg(w + ec);
    }
    #pragma unroll
    for (int k = 0; k < EPT; k++) {
        v[k] = __ldg(reinterpret_cast<const float4*>(g_fx) + s[k] * 2 + p);
    }
    #pragma unroll
    for (int k = 0; k < EPT; k++) {
        int e = base + k * 16;
        if (e < NE) {
            if (p == 0)
                g_packed[e] = ((unsigned)s[k] << 14) | (unsigned)t[k];
            float wk = we[k];
            red_add_v4(g_pred + (size_t)t[k] * 8 + p * 4,
                       make_float4(wk * v[k].x, wk * v[k].y,
                                   wk * v[k].z, wk * v[k].w));
        }
    }
}

// ---------------------------------------------------------------------------
__global__ __launch_bounds__(256) void err_kernel() {
    int i = blockIdx.x * blockDim.x + threadIdx.x;   // float4 index
    if (i >= NB / 4) return;
    const float4* xt4 = reinterpret_cast<const float4*>(g_xt);
    const float4* pr4 = reinterpret_cast<const float4*>(g_pred);
    float4 x = xt4[i], p = pr4[i];
    reinterpret_cast<float4*>(g_err)[i] =
        make_float4(x.x - p.x, x.y - p.y, x.z - p.z, x.w - p.w);
}

// ---------------------------------------------------------------------------
// pass2: aggr[src] += w * err[tgt]  (2 lanes/edge, packed indices)
__global__ __launch_bounds__(256) void pass2_kernel(const float* __restrict__ w) {
    int tid  = blockIdx.x * blockDim.x + threadIdx.x;
    int warp = tid >> 5;
    int lane = tid & 31;
    int p    = lane & 1;
    int eo   = lane >> 1;
    int base = warp * (16 * EPT) + eo;

    int   s[EPT], t[EPT];
    float we[EPT];
    float4 v[EPT];

    #pragma unroll
    for (int k = 0; k < EPT; k++) {
        int e  = base + k * 16;
        int ec = (e < NE) ? e : 0;
        unsigned pk = __ldg(g_packed + ec);
        s[k] = (int)(pk >> 14);
        t[k] = (int)(pk & 16383u);
        we[k] = __ldg(w + ec);
    }
    #pragma unroll
    for (int k = 0; k < EPT; k++) {
        v[k] = __ldg(reinterpret_cast<const float4*>(g_err) + t[k] * 2 + p);
    }
    #pragma unroll
    for (int k = 0; k < EPT; k++) {
        int e = base + k * 16;
        if (e < NE) {
            float wk = we[k];
            red_add_v4(g_aggr + (size_t)s[k] * 8 + p * 4,
                       make_float4(wk * v[k].x, wk * v[k].y,
                                   wk * v[k].z, wk * v[k].w));
        }
    }
}

// ---------------------------------------------------------------------------
// out layout: [3, B*N], inner [B, N] (row b, node n at b*N + n)
__global__ __launch_bounds__(256) void final_kernel(float* __restrict__ out) {
    int n = blockIdx.x * blockDim.x + threadIdx.x;
    if (n >= NV) return;
    const float4* fx4 = reinterpret_cast<const float4*>(g_fx)   + n * 2;
    const float4* pr4 = reinterpret_cast<const float4*>(g_pred) + n * 2;
    const float4* er4 = reinterpret_cast<const float4*>(g_err)  + n * 2;
    const float4* ag4 = reinterpret_cast<const float4*>(g_aggr) + n * 2;
    float fx[8], pr[8], er[8], ag[8];
    float4 t;
    t = fx4[0]; fx[0]=t.x; fx[1]=t.y; fx[2]=t.z; fx[3]=t.w;
    t = fx4[1]; fx[4]=t.x; fx[5]=t.y; fx[6]=t.z; fx[7]=t.w;
    t = pr4[0]; pr[0]=t.x; pr[1]=t.y; pr[2]=t.z; pr[3]=t.w;
    t = pr4[1]; pr[4]=t.x; pr[5]=t.y; pr[6]=t.z; pr[7]=t.w;
    t = er4[0]; er[0]=t.x; er[1]=t.y; er[2]=t.z; er[3]=t.w;
    t = er4[1]; er[4]=t.x; er[5]=t.y; er[6]=t.z; er[7]=t.w;
    t = ag4[0]; ag[0]=t.x; ag[1]=t.y; ag[2]=t.z; ag[3]=t.w;
    t = ag4[1]; ag[4]=t.x; ag[5]=t.y; ag[6]=t.z; ag[7]=t.w;
    #pragma unroll
    for (int b = 0; b < 8; b++) {
        float dx = er[b] - (1.0f - fx[b] * fx[b]) * ag[b];
        int o = b * NV + n;
        out[o]          = pr[b];
        out[NB + o]     = er[b];
        out[2 * NB + o] = dx;
    }
}

// ---------------------------------------------------------------------------
extern "C" void kernel_launch(void* const* d_in, const int* in_sizes, int n_in,
                              void* d_out, int out_size) {
    const float* values  = (const float*)d_in[0];
    const float* weights = (const float*)d_in[1];
    const void*  ei      = (const void*)d_in[2];
    float* out = (float*)d_out;

    const int TB = 256;
    // edge kernels: 1 warp per 16*EPT edges
    int nwarps  = (NE + 16 * EPT - 1) / (16 * EPT);   // 31250
    int nblocks = (nwarps * 32 + TB - 1) / TB;        // 3907

    prep_kernel <<<(NV + TB - 1) / TB, TB>>>(values, (const unsigned int*)ei);
    pass1_kernel<<<nblocks, TB>>>(ei, weights);
    err_kernel  <<<(NB / 4 + TB - 1) / TB, TB>>>();
    pass2_kernel<<<nblocks, TB>>>(weights);
    final_kernel<<<(NV + TB - 1) / TB, TB>>>(out);
}